// round 12
// baseline (speedup 1.0000x reference)
#include <cuda_runtime.h>

#define WARPS_PER_BLOCK 4
#define THREADS 128
#define GRID_BLOCKS 512
#define MAX_BLOCKS 1024

__device__ float g_partials[MAX_BLOCKS * 3];
__device__ unsigned int g_count = 0;

// 16-lane butterfly: both half-warps reduce independently (offsets < 16)
__device__ __forceinline__ float wsum16(float v) {
#pragma unroll
    for (int o = 8; o > 0; o >>= 1) v += __shfl_xor_sync(0xffffffffu, v, o);
    return v;
}

__device__ __forceinline__ float dot4(float4 a, float4 b) {
    return a.x * b.x + a.y * b.y + a.z * b.z + a.w * b.w;
}

// -log(sigmoid(x)) = softplus(-x); fast + stable (tol is 1e-3)
__device__ __forceinline__ float nlsig(float x) {
    float z = -x;
    return fmaxf(z, 0.f) + __logf(1.f + __expf(-fabsf(z)));
}

// L2 prefetch, no destination register, no scoreboard
__device__ __forceinline__ void pf_l2(const void* p) {
    asm volatile("prefetch.global.L2 [%0];" :: "l"(p));
}

struct Ids { int aid, pid, nid, uid, nrid, prid, nrel; };

__device__ __forceinline__ Ids load_ids(
    const int* __restrict__ u_id, const int* __restrict__ anchor_i_id,
    const int* __restrict__ pos_r_id, const int* __restrict__ pos_i_id,
    const int* __restrict__ neg_r_id, const int* __restrict__ neg_i_id,
    const int* __restrict__ neg_ri_id, int b)
{
    Ids s;
    s.aid  = __ldg(anchor_i_id + b);
    s.pid  = __ldg(pos_i_id + b);
    s.nid  = __ldg(neg_i_id + b);
    s.uid  = __ldg(u_id + b);
    s.nrid = __ldg(neg_ri_id + b);
    s.prid = __ldg(pos_r_id + b);
    s.nrel = __ldg(neg_r_id + b);
    return s;
}

__global__ void __launch_bounds__(THREADS, 4) actr_main(
    const int* __restrict__ u_id, const int* __restrict__ anchor_i_id,
    const int* __restrict__ pos_r_id, const int* __restrict__ pos_i_id,
    const int* __restrict__ neg_r_id, const int* __restrict__ neg_i_id,
    const int* __restrict__ neg_ri_id, const int* __restrict__ item_meta,
    const float* __restrict__ user_emb, const float* __restrict__ rel_emb,
    const float* __restrict__ item_emb, const float* __restrict__ item_emb_r,
    const float* __restrict__ item_bias, const float* __restrict__ rel_bias,
    const float* __restrict__ meta_emb,
    const float* __restrict__ att_w_W, const float* __restrict__ att_v_W,
    float* __restrict__ out, int B, float invB)
{
    const int lane = threadIdx.x & 31;
    const int half = lane >> 4;          // which sample of the pair
    const int hl   = lane & 15;          // lane within the 16-lane group
    const int wid  = threadIdx.x >> 5;
    const int S = gridDim.x * WARPS_PER_BLOCK * 2;   // samples per grid stride
    const bool pfl = ((hl & 7) == 0);    // 2 lanes per 256B row -> both 128B lines

    // ---- per-warp w2 prologue (no barrier, no extra launch):
    // lane l computes w2[2l], w2[2l+1]; shuffles redistribute to float4-per-lane.
    float4 w2;
    {
        float s0 = 0.f, s1 = 0.f;
        const float4* v2 = (const float4*)(att_v_W + 64);
        const float4* w0 = (const float4*)(att_w_W + (lane * 2) * 64);
        const float4* w1 = (const float4*)(att_w_W + (lane * 2 + 1) * 64);
#pragma unroll
        for (int e = 0; e < 16; e++) {
            float4 vv = __ldg(v2 + e);
            s0 += dot4(__ldg(w0 + e), vv);
            s1 += dot4(__ldg(w1 + e), vv);
        }
        int src = hl * 2;
        w2.x = __shfl_sync(0xffffffffu, s0, src);
        w2.y = __shfl_sync(0xffffffffu, s1, src);
        w2.z = __shfl_sync(0xffffffffu, s0, src + 1);
        w2.w = __shfl_sync(0xffffffffu, s1, src + 1);
    }

    // ---- loop-invariant data: each lane holds dims [4*hl, 4*hl+3]
    float4 re[3];
    float relb[3];
#pragma unroll
    for (int r = 0; r < 3; r++) {
        re[r] = __ldg((const float4*)rel_emb + r * 16 + hl);
        relb[r] = __ldg(rel_bias + r);
    }

    float accSeq = 0.f, accRel = 0.f, accItm = 0.f;

    int b = (blockIdx.x * WARPS_PER_BLOCK + wid) * 2 + half;
    const int Bm1 = B - 1;

    // ---- pipeline prologue: ids + meta indices for first sample
    Ids cur = load_ids(u_id, anchor_i_id, pos_r_id, pos_i_id, neg_r_id, neg_i_id, neg_ri_id,
                       min(b, Bm1));
    int4 cma = __ldg((const int4*)item_meta + cur.aid);
    int4 cmp = __ldg((const int4*)item_meta + cur.pid);
    int4 cmn = __ldg((const int4*)item_meta + cur.nid);

    while (b < B) {
        const int nb = b + S;

        // ---- issue ALL embedding gathers (indices resolved + L2-prefetched last iter)
        float4 u   = __ldg((const float4*)user_emb   + (size_t)cur.uid  * 16 + hl);
        float4 ar  = __ldg((const float4*)item_emb_r + (size_t)cur.aid  * 16 + hl);
        float4 a   = __ldg((const float4*)item_emb   + (size_t)cur.aid  * 16 + hl);
        float4 p   = __ldg((const float4*)item_emb   + (size_t)cur.pid  * 16 + hl);
        float4 n   = __ldg((const float4*)item_emb   + (size_t)cur.nid  * 16 + hl);
        float4 nri = __ldg((const float4*)item_emb   + (size_t)cur.nrid * 16 + hl);

        const int mai[4] = {cma.x, cma.y, cma.z, cma.w};
        const int mpi[4] = {cmp.x, cmp.y, cmp.z, cmp.w};
        const int mni[4] = {cmn.x, cmn.y, cmn.z, cmn.w};
        float4 am[4], pm[4], nm[4];
#pragma unroll
        for (int g = 0; g < 4; g++) {
            am[g] = __ldg((const float4*)meta_emb + (size_t)mai[g] * 16 + hl);
            pm[g] = __ldg((const float4*)meta_emb + (size_t)mpi[g] * 16 + hl);
            nm[g] = __ldg((const float4*)meta_emb + (size_t)mni[g] * 16 + hl);
        }

        // ---- prefetch NEXT sample's ids (arrive during compute below)
        Ids nxt;
        if (nb < B)
            nxt = load_ids(u_id, anchor_i_id, pos_r_id, pos_i_id, neg_r_id, neg_i_id, neg_ri_id, nb);

        // ---- relation prediction: softmax_r( rel_bias[r] - ||u + a_r - rel_emb[r]||^2 )
        float4 uar;
        uar.x = u.x + ar.x; uar.y = u.y + ar.y; uar.z = u.z + ar.z; uar.w = u.w + ar.w;
        float rw[3];
#pragma unroll
        for (int r = 0; r < 3; r++) {
            float4 d;
            d.x = uar.x - re[r].x; d.y = uar.y - re[r].y;
            d.z = uar.z - re[r].z; d.w = uar.w - re[r].w;
            rw[r] = relb[r] - wsum16(dot4(d, d));
        }
        float mx = fmaxf(rw[0], fmaxf(rw[1], rw[2]));
        float ssum = 0.f;
#pragma unroll
        for (int r = 0; r < 3; r++) { rw[r] = __expf(rw[r] - mx); ssum += rw[r]; }
        float inv = __frcp_rn(ssum);
#pragma unroll
        for (int r = 0; r < 3; r++) rw[r] *= inv;

        // ---- attention coef: softmax_c( i_plus[c] . w2 )
        float cf[5];
        cf[0] = wsum16(dot4(a, w2));
#pragma unroll
        for (int g = 0; g < 4; g++)
            cf[1 + g] = wsum16(dot4(am[g], w2));
        mx = cf[0];
#pragma unroll
        for (int c = 1; c < 5; c++) mx = fmaxf(mx, cf[c]);
        ssum = 0.f;
#pragma unroll
        for (int c = 0; c < 5; c++) { cf[c] = __expf(cf[c] - mx); ssum += cf[c]; }
        inv = __frcp_rn(ssum);
#pragma unroll
        for (int c = 0; c < 5; c++) cf[c] *= inv;

        // ---- next-sample L2 prefetch: user/item rows (ids arrived; no reg cost)
        if (nb < B && pfl) {
            pf_l2((const float4*)user_emb   + (size_t)nxt.uid  * 16 + hl);
            pf_l2((const float4*)item_emb_r + (size_t)nxt.aid  * 16 + hl);
            pf_l2((const float4*)item_emb   + (size_t)nxt.aid  * 16 + hl);
            pf_l2((const float4*)item_emb   + (size_t)nxt.pid  * 16 + hl);
            pf_l2((const float4*)item_emb   + (size_t)nxt.nid  * 16 + hl);
            pf_l2((const float4*)item_emb   + (size_t)nxt.nrid * 16 + hl);
        }

        // ---- prefetch NEXT sample's meta indices (nxt ids have arrived by now)
        int4 nma, nmp, nmn;
        if (nb < B) {
            nma = __ldg((const int4*)item_meta + nxt.aid);
            nmp = __ldg((const int4*)item_meta + nxt.pid);
            nmn = __ldg((const int4*)item_meta + nxt.nid);
        }

        // ---- rbar = sum_r rel[r]*rue[r]  (||rue||^2 term cancels in pos-neg diff)
        const float GAMMA = 0.5f;
        float4 rbar;
        rbar.x = GAMMA * (rw[0] * re[0].x + rw[1] * re[1].x + rw[2] * re[2].x) + (1.f - GAMMA) * u.x;
        rbar.y = GAMMA * (rw[0] * re[0].y + rw[1] * re[1].y + rw[2] * re[2].y) + (1.f - GAMMA) * u.y;
        rbar.z = GAMMA * (rw[0] * re[0].z + rw[1] * re[1].z + rw[2] * re[2].z) + (1.f - GAMMA) * u.z;
        rbar.w = GAMMA * (rw[0] * re[0].w + rw[1] * re[1].w + rw[2] * re[2].w) + (1.f - GAMMA) * u.w;

        // ---- seq score difference in one reduction
        float diffpn;
        {
            float sdp = 0.f, sdn = 0.f;
            float4 dbp = make_float4(0.f, 0.f, 0.f, 0.f);
            float4 dbn = make_float4(0.f, 0.f, 0.f, 0.f);
            float4 d;
            d.x = a.x - p.x; d.y = a.y - p.y; d.z = a.z - p.z; d.w = a.w - p.w;
            sdp += cf[0] * dot4(d, d);
            dbp.x += cf[0] * d.x; dbp.y += cf[0] * d.y; dbp.z += cf[0] * d.z; dbp.w += cf[0] * d.w;
            d.x = a.x - n.x; d.y = a.y - n.y; d.z = a.z - n.z; d.w = a.w - n.w;
            sdn += cf[0] * dot4(d, d);
            dbn.x += cf[0] * d.x; dbn.y += cf[0] * d.y; dbn.z += cf[0] * d.z; dbn.w += cf[0] * d.w;
#pragma unroll
            for (int g = 0; g < 4; g++) {
                float c = cf[1 + g];
                d.x = am[g].x - pm[g].x; d.y = am[g].y - pm[g].y;
                d.z = am[g].z - pm[g].z; d.w = am[g].w - pm[g].w;
                sdp += c * dot4(d, d);
                dbp.x += c * d.x; dbp.y += c * d.y; dbp.z += c * d.z; dbp.w += c * d.w;
                d.x = am[g].x - nm[g].x; d.y = am[g].y - nm[g].y;
                d.z = am[g].z - nm[g].z; d.w = am[g].w - nm[g].w;
                sdn += c * dot4(d, d);
                dbn.x += c * d.x; dbn.y += c * d.y; dbn.z += c * d.z; dbn.w += c * d.w;
            }
            float sp = sdp + 2.f * dot4(dbp, rbar);
            float sn = sdn + 2.f * dot4(dbn, rbar);
            diffpn = wsum16(sp - sn);
        }
        float biasP = __ldg(item_bias + cur.pid);
        float biasN = __ldg(item_bias + cur.nid);

        // ---- next-sample L2 prefetch: meta rows (meta indices just arrived)
        if (nb < B && pfl) {
            pf_l2((const float4*)meta_emb + (size_t)nma.x * 16 + hl);
            pf_l2((const float4*)meta_emb + (size_t)nma.y * 16 + hl);
            pf_l2((const float4*)meta_emb + (size_t)nma.z * 16 + hl);
            pf_l2((const float4*)meta_emb + (size_t)nma.w * 16 + hl);
            pf_l2((const float4*)meta_emb + (size_t)nmp.x * 16 + hl);
            pf_l2((const float4*)meta_emb + (size_t)nmp.y * 16 + hl);
            pf_l2((const float4*)meta_emb + (size_t)nmp.z * 16 + hl);
            pf_l2((const float4*)meta_emb + (size_t)nmp.w * 16 + hl);
            pf_l2((const float4*)meta_emb + (size_t)nmn.x * 16 + hl);
            pf_l2((const float4*)meta_emb + (size_t)nmn.y * 16 + hl);
            pf_l2((const float4*)meta_emb + (size_t)nmn.z * 16 + hl);
            pf_l2((const float4*)meta_emb + (size_t)nmn.w * 16 + hl);
        }

        // ---- item loss distance in one reduction
        float4 iir = (cur.prid == 0) ? re[0] : ((cur.prid == 1) ? re[1] : re[2]);
        float4 pv, qv;
        pv.x = a.x + iir.x - p.x;   pv.y = a.y + iir.y - p.y;
        pv.z = a.z + iir.z - p.z;   pv.w = a.w + iir.w - p.w;
        qv.x = a.x + iir.x - nri.x; qv.y = a.y + iir.y - nri.y;
        qv.z = a.z + iir.z - nri.z; qv.w = a.w + iir.w - nri.w;
        float di = wsum16(dot4(pv, pv) - dot4(qv, qv));
        float biasNR = __ldg(item_bias + cur.nrid);

        // ---- accumulate (b < B guaranteed by loop condition)
        accSeq += nlsig((biasP - biasN) - diffpn);
        float prs = (cur.prid == 0) ? rw[0] : ((cur.prid == 1) ? rw[1] : rw[2]);
        float nrs = (cur.nrel == 0) ? rw[0] : ((cur.nrel == 1) ? rw[1] : rw[2]);
        accRel += nlsig(prs - nrs);
        accItm += nlsig((biasP - biasNR) - di);

        // ---- rotate pipeline
        cur = nxt; cma = nma; cmp = nmp; cmn = nmn;
        b = nb;
    }

    // ---- combine the two half-warp accumulators (deterministic order)
    accSeq += __shfl_xor_sync(0xffffffffu, accSeq, 16);
    accRel += __shfl_xor_sync(0xffffffffu, accRel, 16);
    accItm += __shfl_xor_sync(0xffffffffu, accItm, 16);

    // ---- deterministic block-level partial sum
    __shared__ float sh[WARPS_PER_BLOCK][3];
    __shared__ bool is_last;
    if (lane == 0) { sh[wid][0] = accSeq; sh[wid][1] = accRel; sh[wid][2] = accItm; }
    __syncthreads();
    if (threadIdx.x == 0) {
        float s0 = 0.f, s1 = 0.f, s2 = 0.f;
#pragma unroll
        for (int w = 0; w < WARPS_PER_BLOCK; w++) {
            s0 += sh[w][0]; s1 += sh[w][1]; s2 += sh[w][2];
        }
        g_partials[blockIdx.x * 3 + 0] = s0;
        g_partials[blockIdx.x * 3 + 1] = s1;
        g_partials[blockIdx.x * 3 + 2] = s2;
        __threadfence();
        unsigned int old = atomicAdd(&g_count, 1u);
        is_last = (old == gridDim.x - 1);
    }
    __syncthreads();

    // ---- last arriving block does the final (fixed-order, deterministic) reduce
    if (is_last) {
        const int nblocks = gridDim.x;
        __shared__ float shf[3];
        if (wid < 3) {
            float s = 0.f;
            for (int i = lane; i < nblocks; i += 32) s += g_partials[i * 3 + wid];
#pragma unroll
            for (int o = 16; o > 0; o >>= 1) s += __shfl_xor_sync(0xffffffffu, s, o);
            s *= invB;
            if (lane == 0) shf[wid] = s;
        }
        __syncthreads();
        if (threadIdx.x == 0) {
            float seq = shf[0], rel = shf[1], itm = shf[2];
            out[0] = seq + rel + itm;   // loss (ALPHA=BETA=1)
            out[1] = rel;               // relation_loss
            out[2] = seq;               // seq_loss
            out[3] = itm;               // item_loss
            g_count = 0;                // reset for next graph replay
        }
    }
}

extern "C" void kernel_launch(void* const* d_in, const int* in_sizes, int n_in,
                              void* d_out, int out_size) {
    const int*   u_id       = (const int*)d_in[0];
    const int*   anchor_i   = (const int*)d_in[1];
    const int*   pos_r      = (const int*)d_in[2];
    const int*   pos_i      = (const int*)d_in[3];
    const int*   neg_r      = (const int*)d_in[4];
    const int*   neg_i      = (const int*)d_in[5];
    const int*   neg_ri     = (const int*)d_in[6];
    const int*   item_meta  = (const int*)d_in[7];
    const float* user_emb   = (const float*)d_in[8];
    const float* rel_emb    = (const float*)d_in[9];
    const float* item_emb   = (const float*)d_in[10];
    const float* item_emb_r = (const float*)d_in[11];
    const float* item_bias  = (const float*)d_in[12];
    const float* rel_bias   = (const float*)d_in[13];
    const float* meta_emb   = (const float*)d_in[14];
    const float* att_w_W    = (const float*)d_in[15];
    const float* att_v_W    = (const float*)d_in[17];

    const int B = in_sizes[0];

    actr_main<<<GRID_BLOCKS, THREADS>>>(u_id, anchor_i, pos_r, pos_i, neg_r, neg_i, neg_ri,
                                        item_meta, user_emb, rel_emb, item_emb, item_emb_r,
                                        item_bias, rel_bias, meta_emb, att_w_W, att_v_W,
                                        (float*)d_out, B, 1.0f / (float)B);
}

// round 13
// speedup vs baseline: 1.0332x; 1.0332x over previous
#include <cuda_runtime.h>

#define WARPS_PER_BLOCK 4
#define THREADS 128
#define GRID_BLOCKS 740
#define MAX_BLOCKS 1024

__device__ __align__(16) float g_w2[64];
__device__ float g_partials[MAX_BLOCKS * 3];
__device__ unsigned int g_count = 0;

// 16-lane butterfly: both half-warps reduce independently (offsets < 16)
__device__ __forceinline__ float wsum16(float v) {
#pragma unroll
    for (int o = 8; o > 0; o >>= 1) v += __shfl_xor_sync(0xffffffffu, v, o);
    return v;
}

__device__ __forceinline__ float dot4(float4 a, float4 b) {
    return a.x * b.x + a.y * b.y + a.z * b.z + a.w * b.w;
}

// -log(sigmoid(x)) = softplus(-x); fast + stable (tol is 1e-3)
__device__ __forceinline__ float nlsig(float x) {
    float z = -x;
    return fmaxf(z, 0.f) + __logf(1.f + __expf(-fabsf(z)));
}

// L2 prefetch, no destination register, no scoreboard
__device__ __forceinline__ void pf_l2(const void* p) {
    asm volatile("prefetch.global.L2 [%0];" :: "l"(p));
}

// w2[d] = sum_e att_w_W[d,e] * att_v_W[64+e]  (tiny one-block kernel, runs once)
__global__ void precompute_w2(const float* __restrict__ W, const float* __restrict__ vW) {
    const int d = threadIdx.x;
    const float4* Wr = (const float4*)(W + d * 64);
    const float4* vr = (const float4*)(vW + 64);
    float s = 0.f;
#pragma unroll
    for (int e = 0; e < 16; e++) {
        float4 w = __ldg(Wr + e);
        float4 v = __ldg(vr + e);
        s += w.x * v.x + w.y * v.y + w.z * v.z + w.w * v.w;
    }
    g_w2[d] = s;
}

struct Ids { int aid, pid, nid, uid, nrid, prid, nrel; };

__device__ __forceinline__ Ids load_ids(
    const int* __restrict__ u_id, const int* __restrict__ anchor_i_id,
    const int* __restrict__ pos_r_id, const int* __restrict__ pos_i_id,
    const int* __restrict__ neg_r_id, const int* __restrict__ neg_i_id,
    const int* __restrict__ neg_ri_id, int b)
{
    Ids s;
    s.aid  = __ldg(anchor_i_id + b);
    s.pid  = __ldg(pos_i_id + b);
    s.nid  = __ldg(neg_i_id + b);
    s.uid  = __ldg(u_id + b);
    s.nrid = __ldg(neg_ri_id + b);
    s.prid = __ldg(pos_r_id + b);
    s.nrel = __ldg(neg_r_id + b);
    return s;
}

__global__ void __launch_bounds__(THREADS, 5) actr_main(
    const int* __restrict__ u_id, const int* __restrict__ anchor_i_id,
    const int* __restrict__ pos_r_id, const int* __restrict__ pos_i_id,
    const int* __restrict__ neg_r_id, const int* __restrict__ neg_i_id,
    const int* __restrict__ neg_ri_id, const int* __restrict__ item_meta,
    const float* __restrict__ user_emb, const float* __restrict__ rel_emb,
    const float* __restrict__ item_emb, const float* __restrict__ item_emb_r,
    const float* __restrict__ item_bias, const float* __restrict__ rel_bias,
    const float* __restrict__ meta_emb,
    float* __restrict__ out, int B, float invB)
{
    const int lane = threadIdx.x & 31;
    const int half = lane >> 4;          // which sample of the pair
    const int hl   = lane & 15;          // lane within the 16-lane group
    const int wid  = threadIdx.x >> 5;
    const int S = gridDim.x * WARPS_PER_BLOCK * 2;   // samples per grid stride
    const bool pfl = ((hl & 7) == 0);    // 2 lanes per 256B row -> both 128B lines

    // ---- loop-invariant data: each lane holds dims [4*hl, 4*hl+3]
    float4 w2 = __ldg((const float4*)g_w2 + hl);
    float4 re[3];
    float relb[3];
#pragma unroll
    for (int r = 0; r < 3; r++) {
        re[r] = __ldg((const float4*)rel_emb + r * 16 + hl);
        relb[r] = __ldg(rel_bias + r);
    }

    float accSeq = 0.f, accRel = 0.f, accItm = 0.f;

    int b = (blockIdx.x * WARPS_PER_BLOCK + wid) * 2 + half;
    const int Bm1 = B - 1;

    // ---- pipeline prologue: ids + meta indices for first sample
    Ids cur = load_ids(u_id, anchor_i_id, pos_r_id, pos_i_id, neg_r_id, neg_i_id, neg_ri_id,
                       min(b, Bm1));
    int4 cma = __ldg((const int4*)item_meta + cur.aid);
    int4 cmp = __ldg((const int4*)item_meta + cur.pid);
    int4 cmn = __ldg((const int4*)item_meta + cur.nid);

    while (b < B) {
        const int nb = b + S;

        // ---- issue ALL embedding gathers (indices resolved + L2-prefetched last iter)
        float4 u   = __ldg((const float4*)user_emb   + (size_t)cur.uid  * 16 + hl);
        float4 ar  = __ldg((const float4*)item_emb_r + (size_t)cur.aid  * 16 + hl);
        float4 a   = __ldg((const float4*)item_emb   + (size_t)cur.aid  * 16 + hl);
        float4 p   = __ldg((const float4*)item_emb   + (size_t)cur.pid  * 16 + hl);
        float4 n   = __ldg((const float4*)item_emb   + (size_t)cur.nid  * 16 + hl);
        float4 nri = __ldg((const float4*)item_emb   + (size_t)cur.nrid * 16 + hl);

        const int mai[4] = {cma.x, cma.y, cma.z, cma.w};
        const int mpi[4] = {cmp.x, cmp.y, cmp.z, cmp.w};
        const int mni[4] = {cmn.x, cmn.y, cmn.z, cmn.w};
        float4 am[4], pm[4], nm[4];
#pragma unroll
        for (int g = 0; g < 4; g++) {
            am[g] = __ldg((const float4*)meta_emb + (size_t)mai[g] * 16 + hl);
            pm[g] = __ldg((const float4*)meta_emb + (size_t)mpi[g] * 16 + hl);
            nm[g] = __ldg((const float4*)meta_emb + (size_t)mni[g] * 16 + hl);
        }

        // ---- prefetch NEXT sample's ids (arrive during compute below)
        Ids nxt;
        if (nb < B)
            nxt = load_ids(u_id, anchor_i_id, pos_r_id, pos_i_id, neg_r_id, neg_i_id, neg_ri_id, nb);

        // ---- relation prediction: softmax_r( rel_bias[r] - ||u + a_r - rel_emb[r]||^2 )
        float4 uar;
        uar.x = u.x + ar.x; uar.y = u.y + ar.y; uar.z = u.z + ar.z; uar.w = u.w + ar.w;
        float rw[3];
#pragma unroll
        for (int r = 0; r < 3; r++) {
            float4 d;
            d.x = uar.x - re[r].x; d.y = uar.y - re[r].y;
            d.z = uar.z - re[r].z; d.w = uar.w - re[r].w;
            rw[r] = relb[r] - wsum16(dot4(d, d));
        }
        float mx = fmaxf(rw[0], fmaxf(rw[1], rw[2]));
        float ssum = 0.f;
#pragma unroll
        for (int r = 0; r < 3; r++) { rw[r] = __expf(rw[r] - mx); ssum += rw[r]; }
        float inv = __frcp_rn(ssum);
#pragma unroll
        for (int r = 0; r < 3; r++) rw[r] *= inv;

        // ---- attention coef: softmax_c( i_plus[c] . w2 )
        float cf[5];
        cf[0] = wsum16(dot4(a, w2));
#pragma unroll
        for (int g = 0; g < 4; g++)
            cf[1 + g] = wsum16(dot4(am[g], w2));
        mx = cf[0];
#pragma unroll
        for (int c = 1; c < 5; c++) mx = fmaxf(mx, cf[c]);
        ssum = 0.f;
#pragma unroll
        for (int c = 0; c < 5; c++) { cf[c] = __expf(cf[c] - mx); ssum += cf[c]; }
        inv = __frcp_rn(ssum);
#pragma unroll
        for (int c = 0; c < 5; c++) cf[c] *= inv;

        // ---- next-sample L2 prefetch: user/item rows (ids arrived; no reg cost)
        if (nb < B && pfl) {
            pf_l2((const float4*)user_emb   + (size_t)nxt.uid  * 16 + hl);
            pf_l2((const float4*)item_emb_r + (size_t)nxt.aid  * 16 + hl);
            pf_l2((const float4*)item_emb   + (size_t)nxt.aid  * 16 + hl);
            pf_l2((const float4*)item_emb   + (size_t)nxt.pid  * 16 + hl);
            pf_l2((const float4*)item_emb   + (size_t)nxt.nid  * 16 + hl);
            pf_l2((const float4*)item_emb   + (size_t)nxt.nrid * 16 + hl);
        }

        // ---- prefetch NEXT sample's meta indices (nxt ids have arrived by now)
        int4 nma, nmp, nmn;
        if (nb < B) {
            nma = __ldg((const int4*)item_meta + nxt.aid);
            nmp = __ldg((const int4*)item_meta + nxt.pid);
            nmn = __ldg((const int4*)item_meta + nxt.nid);
        }

        // ---- rbar = sum_r rel[r]*rue[r]  (||rue||^2 term cancels in pos-neg diff)
        const float GAMMA = 0.5f;
        float4 rbar;
        rbar.x = GAMMA * (rw[0] * re[0].x + rw[1] * re[1].x + rw[2] * re[2].x) + (1.f - GAMMA) * u.x;
        rbar.y = GAMMA * (rw[0] * re[0].y + rw[1] * re[1].y + rw[2] * re[2].y) + (1.f - GAMMA) * u.y;
        rbar.z = GAMMA * (rw[0] * re[0].z + rw[1] * re[1].z + rw[2] * re[2].z) + (1.f - GAMMA) * u.z;
        rbar.w = GAMMA * (rw[0] * re[0].w + rw[1] * re[1].w + rw[2] * re[2].w) + (1.f - GAMMA) * u.w;

        // ---- seq score difference in one reduction
        float diffpn;
        {
            float sdp = 0.f, sdn = 0.f;
            float4 dbp = make_float4(0.f, 0.f, 0.f, 0.f);
            float4 dbn = make_float4(0.f, 0.f, 0.f, 0.f);
            float4 d;
            d.x = a.x - p.x; d.y = a.y - p.y; d.z = a.z - p.z; d.w = a.w - p.w;
            sdp += cf[0] * dot4(d, d);
            dbp.x += cf[0] * d.x; dbp.y += cf[0] * d.y; dbp.z += cf[0] * d.z; dbp.w += cf[0] * d.w;
            d.x = a.x - n.x; d.y = a.y - n.y; d.z = a.z - n.z; d.w = a.w - n.w;
            sdn += cf[0] * dot4(d, d);
            dbn.x += cf[0] * d.x; dbn.y += cf[0] * d.y; dbn.z += cf[0] * d.z; dbn.w += cf[0] * d.w;
#pragma unroll
            for (int g = 0; g < 4; g++) {
                float c = cf[1 + g];
                d.x = am[g].x - pm[g].x; d.y = am[g].y - pm[g].y;
                d.z = am[g].z - pm[g].z; d.w = am[g].w - pm[g].w;
                sdp += c * dot4(d, d);
                dbp.x += c * d.x; dbp.y += c * d.y; dbp.z += c * d.z; dbp.w += c * d.w;
                d.x = am[g].x - nm[g].x; d.y = am[g].y - nm[g].y;
                d.z = am[g].z - nm[g].z; d.w = am[g].w - nm[g].w;
                sdn += c * dot4(d, d);
                dbn.x += c * d.x; dbn.y += c * d.y; dbn.z += c * d.z; dbn.w += c * d.w;
            }
            float sp = sdp + 2.f * dot4(dbp, rbar);
            float sn = sdn + 2.f * dot4(dbn, rbar);
            diffpn = wsum16(sp - sn);
        }
        float biasP = __ldg(item_bias + cur.pid);
        float biasN = __ldg(item_bias + cur.nid);

        // ---- next-sample L2 prefetch: meta rows (meta indices just arrived)
        if (nb < B && pfl) {
            pf_l2((const float4*)meta_emb + (size_t)nma.x * 16 + hl);
            pf_l2((const float4*)meta_emb + (size_t)nma.y * 16 + hl);
            pf_l2((const float4*)meta_emb + (size_t)nma.z * 16 + hl);
            pf_l2((const float4*)meta_emb + (size_t)nma.w * 16 + hl);
            pf_l2((const float4*)meta_emb + (size_t)nmp.x * 16 + hl);
            pf_l2((const float4*)meta_emb + (size_t)nmp.y * 16 + hl);
            pf_l2((const float4*)meta_emb + (size_t)nmp.z * 16 + hl);
            pf_l2((const float4*)meta_emb + (size_t)nmp.w * 16 + hl);
            pf_l2((const float4*)meta_emb + (size_t)nmn.x * 16 + hl);
            pf_l2((const float4*)meta_emb + (size_t)nmn.y * 16 + hl);
            pf_l2((const float4*)meta_emb + (size_t)nmn.z * 16 + hl);
            pf_l2((const float4*)meta_emb + (size_t)nmn.w * 16 + hl);
        }

        // ---- item loss distance in one reduction
        float4 iir = (cur.prid == 0) ? re[0] : ((cur.prid == 1) ? re[1] : re[2]);
        float4 pv, qv;
        pv.x = a.x + iir.x - p.x;   pv.y = a.y + iir.y - p.y;
        pv.z = a.z + iir.z - p.z;   pv.w = a.w + iir.w - p.w;
        qv.x = a.x + iir.x - nri.x; qv.y = a.y + iir.y - nri.y;
        qv.z = a.z + iir.z - nri.z; qv.w = a.w + iir.w - nri.w;
        float di = wsum16(dot4(pv, pv) - dot4(qv, qv));
        float biasNR = __ldg(item_bias + cur.nrid);

        // ---- accumulate (b < B guaranteed by loop condition)
        accSeq += nlsig((biasP - biasN) - diffpn);
        float prs = (cur.prid == 0) ? rw[0] : ((cur.prid == 1) ? rw[1] : rw[2]);
        float nrs = (cur.nrel == 0) ? rw[0] : ((cur.nrel == 1) ? rw[1] : rw[2]);
        accRel += nlsig(prs - nrs);
        accItm += nlsig((biasP - biasNR) - di);

        // ---- rotate pipeline
        cur = nxt; cma = nma; cmp = nmp; cmn = nmn;
        b = nb;
    }

    // ---- combine the two half-warp accumulators (deterministic order)
    accSeq += __shfl_xor_sync(0xffffffffu, accSeq, 16);
    accRel += __shfl_xor_sync(0xffffffffu, accRel, 16);
    accItm += __shfl_xor_sync(0xffffffffu, accItm, 16);

    // ---- deterministic block-level partial sum
    __shared__ float sh[WARPS_PER_BLOCK][3];
    __shared__ bool is_last;
    if (lane == 0) { sh[wid][0] = accSeq; sh[wid][1] = accRel; sh[wid][2] = accItm; }
    __syncthreads();
    if (threadIdx.x == 0) {
        float s0 = 0.f, s1 = 0.f, s2 = 0.f;
#pragma unroll
        for (int w = 0; w < WARPS_PER_BLOCK; w++) {
            s0 += sh[w][0]; s1 += sh[w][1]; s2 += sh[w][2];
        }
        g_partials[blockIdx.x * 3 + 0] = s0;
        g_partials[blockIdx.x * 3 + 1] = s1;
        g_partials[blockIdx.x * 3 + 2] = s2;
        __threadfence();
        unsigned int old = atomicAdd(&g_count, 1u);
        is_last = (old == gridDim.x - 1);
    }
    __syncthreads();

    // ---- last arriving block does the final (fixed-order, deterministic) reduce
    if (is_last) {
        const int nblocks = gridDim.x;
        __shared__ float shf[3];
        if (wid < 3) {
            float s = 0.f;
            for (int i = lane; i < nblocks; i += 32) s += g_partials[i * 3 + wid];
#pragma unroll
            for (int o = 16; o > 0; o >>= 1) s += __shfl_xor_sync(0xffffffffu, s, o);
            s *= invB;
            if (lane == 0) shf[wid] = s;
        }
        __syncthreads();
        if (threadIdx.x == 0) {
            float seq = shf[0], rel = shf[1], itm = shf[2];
            out[0] = seq + rel + itm;   // loss (ALPHA=BETA=1)
            out[1] = rel;               // relation_loss
            out[2] = seq;               // seq_loss
            out[3] = itm;               // item_loss
            g_count = 0;                // reset for next graph replay
        }
    }
}

extern "C" void kernel_launch(void* const* d_in, const int* in_sizes, int n_in,
                              void* d_out, int out_size) {
    const int*   u_id       = (const int*)d_in[0];
    const int*   anchor_i   = (const int*)d_in[1];
    const int*   pos_r      = (const int*)d_in[2];
    const int*   pos_i      = (const int*)d_in[3];
    const int*   neg_r      = (const int*)d_in[4];
    const int*   neg_i      = (const int*)d_in[5];
    const int*   neg_ri     = (const int*)d_in[6];
    const int*   item_meta  = (const int*)d_in[7];
    const float* user_emb   = (const float*)d_in[8];
    const float* rel_emb    = (const float*)d_in[9];
    const float* item_emb   = (const float*)d_in[10];
    const float* item_emb_r = (const float*)d_in[11];
    const float* item_bias  = (const float*)d_in[12];
    const float* rel_bias   = (const float*)d_in[13];
    const float* meta_emb   = (const float*)d_in[14];
    const float* att_w_W    = (const float*)d_in[15];
    const float* att_v_W    = (const float*)d_in[17];

    const int B = in_sizes[0];

    precompute_w2<<<1, 64>>>(att_w_W, att_v_W);
    actr_main<<<GRID_BLOCKS, THREADS>>>(u_id, anchor_i, pos_r, pos_i, neg_r, neg_i, neg_ri,
                                        item_meta, user_emb, rel_emb, item_emb, item_emb_r,
                                        item_bias, rel_bias, meta_emb,
                                        (float*)d_out, B, 1.0f / (float)B);
}

// round 14
// speedup vs baseline: 1.2348x; 1.1951x over previous
#include <cuda_runtime.h>

#define WARPS_PER_BLOCK 4
#define THREADS 128
#define GRID_BLOCKS 512
#define MAX_BLOCKS 1024

__device__ __align__(16) float g_w2[64];
__device__ float g_partials[MAX_BLOCKS * 3];
__device__ unsigned int g_count = 0;
__device__ int g_w2_flag = 0;

// 16-lane butterfly: both half-warps reduce independently (offsets < 16)
__device__ __forceinline__ float wsum16(float v) {
#pragma unroll
    for (int o = 8; o > 0; o >>= 1) v += __shfl_xor_sync(0xffffffffu, v, o);
    return v;
}

__device__ __forceinline__ float dot4(float4 a, float4 b) {
    return a.x * b.x + a.y * b.y + a.z * b.z + a.w * b.w;
}

// -log(sigmoid(x)) = softplus(-x); fast + stable (tol is 1e-3)
__device__ __forceinline__ float nlsig(float x) {
    float z = -x;
    return fmaxf(z, 0.f) + __logf(1.f + __expf(-fabsf(z)));
}

// L2 prefetch, no destination register, no scoreboard
__device__ __forceinline__ void pf_l2(const void* p) {
    asm volatile("prefetch.global.L2 [%0];" :: "l"(p));
}

struct Ids { int aid, pid, nid, uid, nrid, prid, nrel; };

__device__ __forceinline__ Ids load_ids(
    const int* __restrict__ u_id, const int* __restrict__ anchor_i_id,
    const int* __restrict__ pos_r_id, const int* __restrict__ pos_i_id,
    const int* __restrict__ neg_r_id, const int* __restrict__ neg_i_id,
    const int* __restrict__ neg_ri_id, int b)
{
    Ids s;
    s.aid  = __ldg(anchor_i_id + b);
    s.pid  = __ldg(pos_i_id + b);
    s.nid  = __ldg(neg_i_id + b);
    s.uid  = __ldg(u_id + b);
    s.nrid = __ldg(neg_ri_id + b);
    s.prid = __ldg(pos_r_id + b);
    s.nrel = __ldg(neg_r_id + b);
    return s;
}

__global__ void __launch_bounds__(THREADS, 4) actr_main(
    const int* __restrict__ u_id, const int* __restrict__ anchor_i_id,
    const int* __restrict__ pos_r_id, const int* __restrict__ pos_i_id,
    const int* __restrict__ neg_r_id, const int* __restrict__ neg_i_id,
    const int* __restrict__ neg_ri_id, const int* __restrict__ item_meta,
    const float* __restrict__ user_emb, const float* __restrict__ rel_emb,
    const float* __restrict__ item_emb, const float* __restrict__ item_emb_r,
    const float* __restrict__ item_bias, const float* __restrict__ rel_bias,
    const float* __restrict__ meta_emb,
    const float* __restrict__ att_w_W, const float* __restrict__ att_v_W,
    float* __restrict__ out, int B, float invB)
{
    const int lane = threadIdx.x & 31;
    const int half = lane >> 4;          // which sample of the pair
    const int hl   = lane & 15;          // lane within the 16-lane group
    const int wid  = threadIdx.x >> 5;
    const int S = gridDim.x * WARPS_PER_BLOCK * 2;   // samples per grid stride
    const bool pfl = ((hl & 7) == 0);    // 2 lanes per 256B row -> both 128B lines

    // ---- w2 producer: block 0 warp 0 ONLY (total chip traffic = 16 KB, once).
    // w2[d] = sum_e att_w_W[d,e] * att_v_W[64+e]; lane computes rows lane, lane+32.
    if (blockIdx.x == 0 && wid == 0) {
        float s0 = 0.f, s1 = 0.f;
        const float4* v2 = (const float4*)(att_v_W + 64);
        const float4* w0 = (const float4*)(att_w_W + lane * 64);
        const float4* w1 = (const float4*)(att_w_W + (lane + 32) * 64);
#pragma unroll
        for (int e = 0; e < 16; e++) {
            float4 vv = __ldg(v2 + e);
            s0 += dot4(__ldg(w0 + e), vv);
            s1 += dot4(__ldg(w1 + e), vv);
        }
        g_w2[lane] = s0;
        g_w2[lane + 32] = s1;
        __threadfence();
        __syncwarp();
        if (lane == 0) atomicExch(&g_w2_flag, 1);
    }

    // ---- loop-invariant data: each lane holds dims [4*hl, 4*hl+3]
    float4 re[3];
    float relb[3];
#pragma unroll
    for (int r = 0; r < 3; r++) {
        re[r] = __ldg((const float4*)rel_emb + r * 16 + hl);
        relb[r] = __ldg(rel_bias + r);
    }

    float accSeq = 0.f, accRel = 0.f, accItm = 0.f;
    float4 w2 = make_float4(0.f, 0.f, 0.f, 0.f);   // loaded after flag on first iter
    bool need_w2 = true;

    int b = (blockIdx.x * WARPS_PER_BLOCK + wid) * 2 + half;
    const int Bm1 = B - 1;

    // ---- pipeline prologue: ids + meta indices for first sample
    Ids cur = load_ids(u_id, anchor_i_id, pos_r_id, pos_i_id, neg_r_id, neg_i_id, neg_ri_id,
                       min(b, Bm1));
    int4 cma = __ldg((const int4*)item_meta + cur.aid);
    int4 cmp = __ldg((const int4*)item_meta + cur.pid);
    int4 cmn = __ldg((const int4*)item_meta + cur.nid);

    while (b < B) {
        const int nb = b + S;

        // ---- issue ALL embedding gathers (indices resolved + L2-prefetched last iter)
        float4 u   = __ldg((const float4*)user_emb   + (size_t)cur.uid  * 16 + hl);
        float4 ar  = __ldg((const float4*)item_emb_r + (size_t)cur.aid  * 16 + hl);
        float4 a   = __ldg((const float4*)item_emb   + (size_t)cur.aid  * 16 + hl);
        float4 p   = __ldg((const float4*)item_emb   + (size_t)cur.pid  * 16 + hl);
        float4 n   = __ldg((const float4*)item_emb   + (size_t)cur.nid  * 16 + hl);
        float4 nri = __ldg((const float4*)item_emb   + (size_t)cur.nrid * 16 + hl);

        const int mai[4] = {cma.x, cma.y, cma.z, cma.w};
        const int mpi[4] = {cmp.x, cmp.y, cmp.z, cmp.w};
        const int mni[4] = {cmn.x, cmn.y, cmn.z, cmn.w};
        float4 am[4], pm[4], nm[4];
#pragma unroll
        for (int g = 0; g < 4; g++) {
            am[g] = __ldg((const float4*)meta_emb + (size_t)mai[g] * 16 + hl);
            pm[g] = __ldg((const float4*)meta_emb + (size_t)mpi[g] * 16 + hl);
            nm[g] = __ldg((const float4*)meta_emb + (size_t)mni[g] * 16 + hl);
        }

        // ---- prefetch NEXT sample's ids (arrive during compute below)
        Ids nxt;
        if (nb < B)
            nxt = load_ids(u_id, anchor_i_id, pos_r_id, pos_i_id, neg_r_id, neg_i_id, neg_ri_id, nb);

        // ---- relation prediction: softmax_r( rel_bias[r] - ||u + a_r - rel_emb[r]||^2 )
        float4 uar;
        uar.x = u.x + ar.x; uar.y = u.y + ar.y; uar.z = u.z + ar.z; uar.w = u.w + ar.w;
        float rw[3];
#pragma unroll
        for (int r = 0; r < 3; r++) {
            float4 d;
            d.x = uar.x - re[r].x; d.y = uar.y - re[r].y;
            d.z = uar.z - re[r].z; d.w = uar.w - re[r].w;
            rw[r] = relb[r] - wsum16(dot4(d, d));
        }
        float mx = fmaxf(rw[0], fmaxf(rw[1], rw[2]));
        float ssum = 0.f;
#pragma unroll
        for (int r = 0; r < 3; r++) { rw[r] = __expf(rw[r] - mx); ssum += rw[r]; }
        float inv = __frcp_rn(ssum);
#pragma unroll
        for (int r = 0; r < 3; r++) rw[r] *= inv;

        // ---- first iteration only: wait for w2 (spin hidden behind the work above)
        if (need_w2) {
            if (lane == 0) {
                while (atomicAdd(&g_w2_flag, 0) == 0) {}
            }
            __syncwarp();
            __threadfence();
            w2 = __ldg((const float4*)g_w2 + hl);
            need_w2 = false;
        }

        // ---- attention coef: softmax_c( i_plus[c] . w2 )
        float cf[5];
        cf[0] = wsum16(dot4(a, w2));
#pragma unroll
        for (int g = 0; g < 4; g++)
            cf[1 + g] = wsum16(dot4(am[g], w2));
        mx = cf[0];
#pragma unroll
        for (int c = 1; c < 5; c++) mx = fmaxf(mx, cf[c]);
        ssum = 0.f;
#pragma unroll
        for (int c = 0; c < 5; c++) { cf[c] = __expf(cf[c] - mx); ssum += cf[c]; }
        inv = __frcp_rn(ssum);
#pragma unroll
        for (int c = 0; c < 5; c++) cf[c] *= inv;

        // ---- next-sample L2 prefetch: user/item rows (ids arrived; no reg cost)
        if (nb < B && pfl) {
            pf_l2((const float4*)user_emb   + (size_t)nxt.uid  * 16 + hl);
            pf_l2((const float4*)item_emb_r + (size_t)nxt.aid  * 16 + hl);
            pf_l2((const float4*)item_emb   + (size_t)nxt.aid  * 16 + hl);
            pf_l2((const float4*)item_emb   + (size_t)nxt.pid  * 16 + hl);
            pf_l2((const float4*)item_emb   + (size_t)nxt.nid  * 16 + hl);
            pf_l2((const float4*)item_emb   + (size_t)nxt.nrid * 16 + hl);
        }

        // ---- prefetch NEXT sample's meta indices (nxt ids have arrived by now)
        int4 nma, nmp, nmn;
        if (nb < B) {
            nma = __ldg((const int4*)item_meta + nxt.aid);
            nmp = __ldg((const int4*)item_meta + nxt.pid);
            nmn = __ldg((const int4*)item_meta + nxt.nid);
        }

        // ---- rbar = sum_r rel[r]*rue[r]  (||rue||^2 term cancels in pos-neg diff)
        const float GAMMA = 0.5f;
        float4 rbar;
        rbar.x = GAMMA * (rw[0] * re[0].x + rw[1] * re[1].x + rw[2] * re[2].x) + (1.f - GAMMA) * u.x;
        rbar.y = GAMMA * (rw[0] * re[0].y + rw[1] * re[1].y + rw[2] * re[2].y) + (1.f - GAMMA) * u.y;
        rbar.z = GAMMA * (rw[0] * re[0].z + rw[1] * re[1].z + rw[2] * re[2].z) + (1.f - GAMMA) * u.z;
        rbar.w = GAMMA * (rw[0] * re[0].w + rw[1] * re[1].w + rw[2] * re[2].w) + (1.f - GAMMA) * u.w;

        // ---- seq score difference in one reduction
        float diffpn;
        {
            float sdp = 0.f, sdn = 0.f;
            float4 dbp = make_float4(0.f, 0.f, 0.f, 0.f);
            float4 dbn = make_float4(0.f, 0.f, 0.f, 0.f);
            float4 d;
            d.x = a.x - p.x; d.y = a.y - p.y; d.z = a.z - p.z; d.w = a.w - p.w;
            sdp += cf[0] * dot4(d, d);
            dbp.x += cf[0] * d.x; dbp.y += cf[0] * d.y; dbp.z += cf[0] * d.z; dbp.w += cf[0] * d.w;
            d.x = a.x - n.x; d.y = a.y - n.y; d.z = a.z - n.z; d.w = a.w - n.w;
            sdn += cf[0] * dot4(d, d);
            dbn.x += cf[0] * d.x; dbn.y += cf[0] * d.y; dbn.z += cf[0] * d.z; dbn.w += cf[0] * d.w;
#pragma unroll
            for (int g = 0; g < 4; g++) {
                float c = cf[1 + g];
                d.x = am[g].x - pm[g].x; d.y = am[g].y - pm[g].y;
                d.z = am[g].z - pm[g].z; d.w = am[g].w - pm[g].w;
                sdp += c * dot4(d, d);
                dbp.x += c * d.x; dbp.y += c * d.y; dbp.z += c * d.z; dbp.w += c * d.w;
                d.x = am[g].x - nm[g].x; d.y = am[g].y - nm[g].y;
                d.z = am[g].z - nm[g].z; d.w = am[g].w - nm[g].w;
                sdn += c * dot4(d, d);
                dbn.x += c * d.x; dbn.y += c * d.y; dbn.z += c * d.z; dbn.w += c * d.w;
            }
            float sp = sdp + 2.f * dot4(dbp, rbar);
            float sn = sdn + 2.f * dot4(dbn, rbar);
            diffpn = wsum16(sp - sn);
        }
        float biasP = __ldg(item_bias + cur.pid);
        float biasN = __ldg(item_bias + cur.nid);

        // ---- next-sample L2 prefetch: meta rows (meta indices just arrived)
        if (nb < B && pfl) {
            pf_l2((const float4*)meta_emb + (size_t)nma.x * 16 + hl);
            pf_l2((const float4*)meta_emb + (size_t)nma.y * 16 + hl);
            pf_l2((const float4*)meta_emb + (size_t)nma.z * 16 + hl);
            pf_l2((const float4*)meta_emb + (size_t)nma.w * 16 + hl);
            pf_l2((const float4*)meta_emb + (size_t)nmp.x * 16 + hl);
            pf_l2((const float4*)meta_emb + (size_t)nmp.y * 16 + hl);
            pf_l2((const float4*)meta_emb + (size_t)nmp.z * 16 + hl);
            pf_l2((const float4*)meta_emb + (size_t)nmp.w * 16 + hl);
            pf_l2((const float4*)meta_emb + (size_t)nmn.x * 16 + hl);
            pf_l2((const float4*)meta_emb + (size_t)nmn.y * 16 + hl);
            pf_l2((const float4*)meta_emb + (size_t)nmn.z * 16 + hl);
            pf_l2((const float4*)meta_emb + (size_t)nmn.w * 16 + hl);
        }

        // ---- item loss distance in one reduction
        float4 iir = (cur.prid == 0) ? re[0] : ((cur.prid == 1) ? re[1] : re[2]);
        float4 pv, qv;
        pv.x = a.x + iir.x - p.x;   pv.y = a.y + iir.y - p.y;
        pv.z = a.z + iir.z - p.z;   pv.w = a.w + iir.w - p.w;
        qv.x = a.x + iir.x - nri.x; qv.y = a.y + iir.y - nri.y;
        qv.z = a.z + iir.z - nri.z; qv.w = a.w + iir.w - nri.w;
        float di = wsum16(dot4(pv, pv) - dot4(qv, qv));
        float biasNR = __ldg(item_bias + cur.nrid);

        // ---- accumulate (b < B guaranteed by loop condition)
        accSeq += nlsig((biasP - biasN) - diffpn);
        float prs = (cur.prid == 0) ? rw[0] : ((cur.prid == 1) ? rw[1] : rw[2]);
        float nrs = (cur.nrel == 0) ? rw[0] : ((cur.nrel == 1) ? rw[1] : rw[2]);
        accRel += nlsig(prs - nrs);
        accItm += nlsig((biasP - biasNR) - di);

        // ---- rotate pipeline
        cur = nxt; cma = nma; cmp = nmp; cmn = nmn;
        b = nb;
    }

    // ---- combine the two half-warp accumulators (deterministic order)
    accSeq += __shfl_xor_sync(0xffffffffu, accSeq, 16);
    accRel += __shfl_xor_sync(0xffffffffu, accRel, 16);
    accItm += __shfl_xor_sync(0xffffffffu, accItm, 16);

    // ---- deterministic block-level partial sum
    __shared__ float sh[WARPS_PER_BLOCK][3];
    __shared__ bool is_last;
    if (lane == 0) { sh[wid][0] = accSeq; sh[wid][1] = accRel; sh[wid][2] = accItm; }
    __syncthreads();
    if (threadIdx.x == 0) {
        float s0 = 0.f, s1 = 0.f, s2 = 0.f;
#pragma unroll
        for (int w = 0; w < WARPS_PER_BLOCK; w++) {
            s0 += sh[w][0]; s1 += sh[w][1]; s2 += sh[w][2];
        }
        g_partials[blockIdx.x * 3 + 0] = s0;
        g_partials[blockIdx.x * 3 + 1] = s1;
        g_partials[blockIdx.x * 3 + 2] = s2;
        __threadfence();
        unsigned int old = atomicAdd(&g_count, 1u);
        is_last = (old == gridDim.x - 1);
    }
    __syncthreads();

    // ---- last arriving block does the final (fixed-order, deterministic) reduce
    if (is_last) {
        const int nblocks = gridDim.x;
        __shared__ float shf[3];
        if (wid < 3) {
            float s = 0.f;
            for (int i = lane; i < nblocks; i += 32) s += g_partials[i * 3 + wid];
#pragma unroll
            for (int o = 16; o > 0; o >>= 1) s += __shfl_xor_sync(0xffffffffu, s, o);
            s *= invB;
            if (lane == 0) shf[wid] = s;
        }
        __syncthreads();
        if (threadIdx.x == 0) {
            float seq = shf[0], rel = shf[1], itm = shf[2];
            out[0] = seq + rel + itm;   // loss (ALPHA=BETA=1)
            out[1] = rel;               // relation_loss
            out[2] = seq;               // seq_loss
            out[3] = itm;               // item_loss
            g_count = 0;                // reset for next graph replay
            g_w2_flag = 0;              // reset w2 gate for next replay
        }
    }
}

extern "C" void kernel_launch(void* const* d_in, const int* in_sizes, int n_in,
                              void* d_out, int out_size) {
    const int*   u_id       = (const int*)d_in[0];
    const int*   anchor_i   = (const int*)d_in[1];
    const int*   pos_r      = (const int*)d_in[2];
    const int*   pos_i      = (const int*)d_in[3];
    const int*   neg_r      = (const int*)d_in[4];
    const int*   neg_i      = (const int*)d_in[5];
    const int*   neg_ri     = (const int*)d_in[6];
    const int*   item_meta  = (const int*)d_in[7];
    const float* user_emb   = (const float*)d_in[8];
    const float* rel_emb    = (const float*)d_in[9];
    const float* item_emb   = (const float*)d_in[10];
    const float* item_emb_r = (const float*)d_in[11];
    const float* item_bias  = (const float*)d_in[12];
    const float* rel_bias   = (const float*)d_in[13];
    const float* meta_emb   = (const float*)d_in[14];
    const float* att_w_W    = (const float*)d_in[15];
    const float* att_v_W    = (const float*)d_in[17];

    const int B = in_sizes[0];

    actr_main<<<GRID_BLOCKS, THREADS>>>(u_id, anchor_i, pos_r, pos_i, neg_r, neg_i, neg_ri,
                                        item_meta, user_emb, rel_emb, item_emb, item_emb_r,
                                        item_bias, rel_bias, meta_emb, att_w_W, att_v_W,
                                        (float*)d_out, B, 1.0f / (float)B);
}

// round 15
// speedup vs baseline: 1.3706x; 1.1100x over previous
#include <cuda_runtime.h>

#define WARPS_PER_BLOCK 4
#define THREADS 128
#define GRID_BLOCKS 512
#define MAX_BLOCKS 1024

typedef unsigned long long ull;

__device__ __align__(16) float g_w2[64];
__device__ float g_partials[MAX_BLOCKS * 3];
__device__ unsigned int g_count = 0;

// ---- packed f32x2 primitives (sm_103a; full fp32 precision per half)
__device__ __forceinline__ ull PK(float lo, float hi) {
    ull r; asm("mov.b64 %0, {%1, %2};" : "=l"(r) : "f"(lo), "f"(hi)); return r;
}
__device__ __forceinline__ float2 UPK(ull v) {
    float2 f; asm("mov.b64 {%0, %1}, %2;" : "=f"(f.x), "=f"(f.y) : "l"(v)); return f;
}
__device__ __forceinline__ ull ADD2(ull a, ull b) {
    ull r; asm("add.rn.f32x2 %0, %1, %2;" : "=l"(r) : "l"(a), "l"(b)); return r;
}
__device__ __forceinline__ ull MUL2(ull a, ull b) {
    ull r; asm("mul.rn.f32x2 %0, %1, %2;" : "=l"(r) : "l"(a), "l"(b)); return r;
}
__device__ __forceinline__ ull FMA2(ull a, ull b, ull c) {
    ull r; asm("fma.rn.f32x2 %0, %1, %2, %3;" : "=l"(r) : "l"(a), "l"(b), "l"(c)); return r;
}
__device__ __forceinline__ float FOLD(ull v) { float2 f = UPK(v); return f.x + f.y; }

struct R2 { ull lo, hi; };   // one 16B row-slice: (d0,d1),(d2,d3)

// 16-lane butterfly: both half-warps reduce independently (offsets < 16)
__device__ __forceinline__ float wsum16(float v) {
#pragma unroll
    for (int o = 8; o > 0; o >>= 1) v += __shfl_xor_sync(0xffffffffu, v, o);
    return v;
}

// -log(sigmoid(x)) = softplus(-x); fast + stable (tol is 1e-3)
__device__ __forceinline__ float nlsig(float x) {
    float z = -x;
    return fmaxf(z, 0.f) + __logf(1.f + __expf(-fabsf(z)));
}

// L2 prefetch, no destination register, no scoreboard
__device__ __forceinline__ void pf_l2(const void* p) {
    asm volatile("prefetch.global.L2 [%0];" :: "l"(p));
}

__device__ __forceinline__ R2 ldrow(const float* base, size_t row, int hl) {
    ulonglong2 t = __ldg((const ulonglong2*)base + row * 16 + hl);
    R2 r; r.lo = t.x; r.hi = t.y; return r;
}

__device__ __forceinline__ float dot4(float4 a, float4 b) {
    return a.x * b.x + a.y * b.y + a.z * b.z + a.w * b.w;
}

// w2[d] = sum_e att_w_W[d,e] * att_v_W[64+e]  (tiny one-block kernel, runs once)
__global__ void precompute_w2(const float* __restrict__ W, const float* __restrict__ vW) {
    const int d = threadIdx.x;
    const float4* Wr = (const float4*)(W + d * 64);
    const float4* vr = (const float4*)(vW + 64);
    float s = 0.f;
#pragma unroll
    for (int e = 0; e < 16; e++) {
        float4 w = __ldg(Wr + e);
        float4 v = __ldg(vr + e);
        s += w.x * v.x + w.y * v.y + w.z * v.z + w.w * v.w;
    }
    g_w2[d] = s;
}

struct Ids { int aid, pid, nid, uid, nrid, prid, nrel; };

__device__ __forceinline__ Ids load_ids(
    const int* __restrict__ u_id, const int* __restrict__ anchor_i_id,
    const int* __restrict__ pos_r_id, const int* __restrict__ pos_i_id,
    const int* __restrict__ neg_r_id, const int* __restrict__ neg_i_id,
    const int* __restrict__ neg_ri_id, int b)
{
    Ids s;
    s.aid  = __ldg(anchor_i_id + b);
    s.pid  = __ldg(pos_i_id + b);
    s.nid  = __ldg(neg_i_id + b);
    s.uid  = __ldg(u_id + b);
    s.nrid = __ldg(neg_ri_id + b);
    s.prid = __ldg(pos_r_id + b);
    s.nrel = __ldg(neg_r_id + b);
    return s;
}

__global__ void __launch_bounds__(THREADS, 4) actr_main(
    const int* __restrict__ u_id, const int* __restrict__ anchor_i_id,
    const int* __restrict__ pos_r_id, const int* __restrict__ pos_i_id,
    const int* __restrict__ neg_r_id, const int* __restrict__ neg_i_id,
    const int* __restrict__ neg_ri_id, const int* __restrict__ item_meta,
    const float* __restrict__ user_emb, const float* __restrict__ rel_emb,
    const float* __restrict__ item_emb, const float* __restrict__ item_emb_r,
    const float* __restrict__ item_bias, const float* __restrict__ rel_bias,
    const float* __restrict__ meta_emb,
    float* __restrict__ out, int B, float invB)
{
    const int lane = threadIdx.x & 31;
    const int half = lane >> 4;          // which sample of the pair
    const int hl   = lane & 15;          // lane within the 16-lane group
    const int wid  = threadIdx.x >> 5;
    const int S = gridDim.x * WARPS_PER_BLOCK * 2;   // samples per grid stride
    const bool pfl = ((hl & 7) == 0);    // 2 lanes per 256B row -> both 128B lines

    const ull NEG1 = PK(-1.f, -1.f);
    const ull HALF2 = PK(0.5f, 0.5f);    // GAMMA = 1-GAMMA = 0.5

    // ---- loop-invariant data: each lane holds dims [4*hl, 4*hl+3]
    R2 w2 = ldrow(g_w2, 0, hl);
    R2 re2[3];
    float relb[3];
#pragma unroll
    for (int r = 0; r < 3; r++) {
        re2[r] = ldrow(rel_emb, r, hl);
        relb[r] = __ldg(rel_bias + r);
    }

    float accSeq = 0.f, accRel = 0.f, accItm = 0.f;

    int b = (blockIdx.x * WARPS_PER_BLOCK + wid) * 2 + half;
    const int Bm1 = B - 1;

    // ---- pipeline prologue: ids + meta indices for first sample
    Ids cur = load_ids(u_id, anchor_i_id, pos_r_id, pos_i_id, neg_r_id, neg_i_id, neg_ri_id,
                       min(b, Bm1));
    int4 cma = __ldg((const int4*)item_meta + cur.aid);
    int4 cmp = __ldg((const int4*)item_meta + cur.pid);
    int4 cmn = __ldg((const int4*)item_meta + cur.nid);

    while (b < B) {
        const int nb = b + S;

        // ---- issue ALL embedding gathers (indices resolved + L2-prefetched last iter)
        R2 u   = ldrow(user_emb,   (size_t)cur.uid,  hl);
        R2 ar  = ldrow(item_emb_r, (size_t)cur.aid,  hl);
        R2 a   = ldrow(item_emb,   (size_t)cur.aid,  hl);
        R2 p   = ldrow(item_emb,   (size_t)cur.pid,  hl);
        R2 n   = ldrow(item_emb,   (size_t)cur.nid,  hl);
        R2 nri = ldrow(item_emb,   (size_t)cur.nrid, hl);

        const int mai[4] = {cma.x, cma.y, cma.z, cma.w};
        const int mpi[4] = {cmp.x, cmp.y, cmp.z, cmp.w};
        const int mni[4] = {cmn.x, cmn.y, cmn.z, cmn.w};
        R2 am[4], pm[4], nm[4];
#pragma unroll
        for (int g = 0; g < 4; g++) {
            am[g] = ldrow(meta_emb, (size_t)mai[g], hl);
            pm[g] = ldrow(meta_emb, (size_t)mpi[g], hl);
            nm[g] = ldrow(meta_emb, (size_t)mni[g], hl);
        }

        // ---- prefetch NEXT sample's ids (arrive during compute below)
        Ids nxt;
        if (nb < B)
            nxt = load_ids(u_id, anchor_i_id, pos_r_id, pos_i_id, neg_r_id, neg_i_id, neg_ri_id, nb);

        // ---- relation prediction: softmax_r( rel_bias[r] - ||u + a_r - rel_emb[r]||^2 )
        R2 uar; uar.lo = ADD2(u.lo, ar.lo); uar.hi = ADD2(u.hi, ar.hi);
        float rw[3];
#pragma unroll
        for (int r = 0; r < 3; r++) {
            ull dl = FMA2(re2[r].lo, NEG1, uar.lo);
            ull dh = FMA2(re2[r].hi, NEG1, uar.hi);
            ull dd = MUL2(dl, dl);
            dd = FMA2(dh, dh, dd);
            rw[r] = relb[r] - wsum16(FOLD(dd));
        }
        float mx = fmaxf(rw[0], fmaxf(rw[1], rw[2]));
        float ssum = 0.f;
#pragma unroll
        for (int r = 0; r < 3; r++) { rw[r] = __expf(rw[r] - mx); ssum += rw[r]; }
        float inv = __frcp_rn(ssum);
#pragma unroll
        for (int r = 0; r < 3; r++) rw[r] *= inv;

        // ---- attention coef: softmax_c( i_plus[c] . w2 )
        float cf[5];
        {
            ull t = MUL2(a.lo, w2.lo); t = FMA2(a.hi, w2.hi, t);
            cf[0] = wsum16(FOLD(t));
        }
#pragma unroll
        for (int g = 0; g < 4; g++) {
            ull t = MUL2(am[g].lo, w2.lo); t = FMA2(am[g].hi, w2.hi, t);
            cf[1 + g] = wsum16(FOLD(t));
        }
        mx = cf[0];
#pragma unroll
        for (int c = 1; c < 5; c++) mx = fmaxf(mx, cf[c]);
        ssum = 0.f;
#pragma unroll
        for (int c = 0; c < 5; c++) { cf[c] = __expf(cf[c] - mx); ssum += cf[c]; }
        inv = __frcp_rn(ssum);
#pragma unroll
        for (int c = 0; c < 5; c++) cf[c] *= inv;

        // ---- next-sample L2 prefetch: user/item rows (ids arrived; no reg cost)
        if (nb < B && pfl) {
            pf_l2((const float4*)user_emb   + (size_t)nxt.uid  * 16 + hl);
            pf_l2((const float4*)item_emb_r + (size_t)nxt.aid  * 16 + hl);
            pf_l2((const float4*)item_emb   + (size_t)nxt.aid  * 16 + hl);
            pf_l2((const float4*)item_emb   + (size_t)nxt.pid  * 16 + hl);
            pf_l2((const float4*)item_emb   + (size_t)nxt.nid  * 16 + hl);
            pf_l2((const float4*)item_emb   + (size_t)nxt.nrid * 16 + hl);
        }

        // ---- prefetch NEXT sample's meta indices (nxt ids have arrived by now)
        int4 nma, nmp, nmn;
        if (nb < B) {
            nma = __ldg((const int4*)item_meta + nxt.aid);
            nmp = __ldg((const int4*)item_meta + nxt.pid);
            nmn = __ldg((const int4*)item_meta + nxt.nid);
        }

        // ---- rbar = 0.5*( sum_r rw[r]*re[r] + u )   (GAMMA = 0.5)
        ull rw0 = PK(rw[0], rw[0]);
        ull rw1 = PK(rw[1], rw[1]);
        ull rw2 = PK(rw[2], rw[2]);
        R2 rbar;
        {
            ull t = MUL2(rw0, re2[0].lo); t = FMA2(rw1, re2[1].lo, t); t = FMA2(rw2, re2[2].lo, t);
            rbar.lo = MUL2(HALF2, ADD2(t, u.lo));
            t = MUL2(rw0, re2[0].hi); t = FMA2(rw1, re2[1].hi, t); t = FMA2(rw2, re2[2].hi, t);
            rbar.hi = MUL2(HALF2, ADD2(t, u.hi));
        }

        // ---- seq score difference in one reduction (srp & ||rue||^2 cancel)
        float diffpn;
        {
            ull sdp2 = 0, sdn2 = 0;
            R2 dbp; dbp.lo = 0; dbp.hi = 0;
            R2 dbn; dbn.lo = 0; dbn.hi = 0;
            ull c2 = PK(cf[0], cf[0]);
            // anchor vs p
            ull dl = FMA2(p.lo, NEG1, a.lo);
            ull dh = FMA2(p.hi, NEG1, a.hi);
            ull dd = MUL2(dl, dl); dd = FMA2(dh, dh, dd);
            sdp2 = FMA2(c2, dd, sdp2);
            dbp.lo = FMA2(c2, dl, dbp.lo); dbp.hi = FMA2(c2, dh, dbp.hi);
            // anchor vs n
            dl = FMA2(n.lo, NEG1, a.lo);
            dh = FMA2(n.hi, NEG1, a.hi);
            dd = MUL2(dl, dl); dd = FMA2(dh, dh, dd);
            sdn2 = FMA2(c2, dd, sdn2);
            dbn.lo = FMA2(c2, dl, dbn.lo); dbn.hi = FMA2(c2, dh, dbn.hi);
#pragma unroll
            for (int g = 0; g < 4; g++) {
                c2 = PK(cf[1 + g], cf[1 + g]);
                dl = FMA2(pm[g].lo, NEG1, am[g].lo);
                dh = FMA2(pm[g].hi, NEG1, am[g].hi);
                dd = MUL2(dl, dl); dd = FMA2(dh, dh, dd);
                sdp2 = FMA2(c2, dd, sdp2);
                dbp.lo = FMA2(c2, dl, dbp.lo); dbp.hi = FMA2(c2, dh, dbp.hi);
                dl = FMA2(nm[g].lo, NEG1, am[g].lo);
                dh = FMA2(nm[g].hi, NEG1, am[g].hi);
                dd = MUL2(dl, dl); dd = FMA2(dh, dh, dd);
                sdn2 = FMA2(c2, dd, sdn2);
                dbn.lo = FMA2(c2, dl, dbn.lo); dbn.hi = FMA2(c2, dh, dbn.hi);
            }
            ull tp = MUL2(dbp.lo, rbar.lo); tp = FMA2(dbp.hi, rbar.hi, tp);
            ull tn = MUL2(dbn.lo, rbar.lo); tn = FMA2(dbn.hi, rbar.hi, tn);
            float sp = FOLD(sdp2) + 2.f * FOLD(tp);
            float sn = FOLD(sdn2) + 2.f * FOLD(tn);
            diffpn = wsum16(sp - sn);
        }
        float biasP = __ldg(item_bias + cur.pid);
        float biasN = __ldg(item_bias + cur.nid);

        // ---- next-sample L2 prefetch: meta rows (meta indices just arrived)
        if (nb < B && pfl) {
            pf_l2((const float4*)meta_emb + (size_t)nma.x * 16 + hl);
            pf_l2((const float4*)meta_emb + (size_t)nma.y * 16 + hl);
            pf_l2((const float4*)meta_emb + (size_t)nma.z * 16 + hl);
            pf_l2((const float4*)meta_emb + (size_t)nma.w * 16 + hl);
            pf_l2((const float4*)meta_emb + (size_t)nmp.x * 16 + hl);
            pf_l2((const float4*)meta_emb + (size_t)nmp.y * 16 + hl);
            pf_l2((const float4*)meta_emb + (size_t)nmp.z * 16 + hl);
            pf_l2((const float4*)meta_emb + (size_t)nmp.w * 16 + hl);
            pf_l2((const float4*)meta_emb + (size_t)nmn.x * 16 + hl);
            pf_l2((const float4*)meta_emb + (size_t)nmn.y * 16 + hl);
            pf_l2((const float4*)meta_emb + (size_t)nmn.z * 16 + hl);
            pf_l2((const float4*)meta_emb + (size_t)nmn.w * 16 + hl);
        }

        // ---- item loss distance in one reduction
        R2 iir = (cur.prid == 0) ? re2[0] : ((cur.prid == 1) ? re2[1] : re2[2]);
        {
            ull pvl = ADD2(a.lo, iir.lo); pvl = FMA2(p.lo, NEG1, pvl);
            ull pvh = ADD2(a.hi, iir.hi); pvh = FMA2(p.hi, NEG1, pvh);
            ull qvl = ADD2(a.lo, iir.lo); qvl = FMA2(nri.lo, NEG1, qvl);
            ull qvh = ADD2(a.hi, iir.hi); qvh = FMA2(nri.hi, NEG1, qvh);
            ull ddp = MUL2(pvl, pvl); ddp = FMA2(pvh, pvh, ddp);
            ull ddq = MUL2(qvl, qvl); ddq = FMA2(qvh, qvh, ddq);
            float di = wsum16(FOLD(ddp) - FOLD(ddq));
            float biasNR = __ldg(item_bias + cur.nrid);

            // ---- accumulate (b < B guaranteed by loop condition)
            accSeq += nlsig((biasP - biasN) - diffpn);
            float prs = (cur.prid == 0) ? rw[0] : ((cur.prid == 1) ? rw[1] : rw[2]);
            float nrs = (cur.nrel == 0) ? rw[0] : ((cur.nrel == 1) ? rw[1] : rw[2]);
            accRel += nlsig(prs - nrs);
            accItm += nlsig((biasP - biasNR) - di);
        }

        // ---- rotate pipeline
        cur = nxt; cma = nma; cmp = nmp; cmn = nmn;
        b = nb;
    }

    // ---- combine the two half-warp accumulators (deterministic order)
    accSeq += __shfl_xor_sync(0xffffffffu, accSeq, 16);
    accRel += __shfl_xor_sync(0xffffffffu, accRel, 16);
    accItm += __shfl_xor_sync(0xffffffffu, accItm, 16);

    // ---- deterministic block-level partial sum
    __shared__ float sh[WARPS_PER_BLOCK][3];
    __shared__ bool is_last;
    if (lane == 0) { sh[wid][0] = accSeq; sh[wid][1] = accRel; sh[wid][2] = accItm; }
    __syncthreads();
    if (threadIdx.x == 0) {
        float s0 = 0.f, s1 = 0.f, s2 = 0.f;
#pragma unroll
        for (int w = 0; w < WARPS_PER_BLOCK; w++) {
            s0 += sh[w][0]; s1 += sh[w][1]; s2 += sh[w][2];
        }
        g_partials[blockIdx.x * 3 + 0] = s0;
        g_partials[blockIdx.x * 3 + 1] = s1;
        g_partials[blockIdx.x * 3 + 2] = s2;
        __threadfence();
        unsigned int old = atomicAdd(&g_count, 1u);
        is_last = (old == gridDim.x - 1);
    }
    __syncthreads();

    // ---- last arriving block does the final (fixed-order, deterministic) reduce
    if (is_last) {
        const int nblocks = gridDim.x;
        __shared__ float shf[3];
        if (wid < 3) {
            float s = 0.f;
            for (int i = lane; i < nblocks; i += 32) s += g_partials[i * 3 + wid];
#pragma unroll
            for (int o = 16; o > 0; o >>= 1) s += __shfl_xor_sync(0xffffffffu, s, o);
            s *= invB;
            if (lane == 0) shf[wid] = s;
        }
        __syncthreads();
        if (threadIdx.x == 0) {
            float seq = shf[0], rel = shf[1], itm = shf[2];
            out[0] = seq + rel + itm;   // loss (ALPHA=BETA=1)
            out[1] = rel;               // relation_loss
            out[2] = seq;               // seq_loss
            out[3] = itm;               // item_loss
            g_count = 0;                // reset for next graph replay
        }
    }
}

extern "C" void kernel_launch(void* const* d_in, const int* in_sizes, int n_in,
                              void* d_out, int out_size) {
    const int*   u_id       = (const int*)d_in[0];
    const int*   anchor_i   = (const int*)d_in[1];
    const int*   pos_r      = (const int*)d_in[2];
    const int*   pos_i      = (const int*)d_in[3];
    const int*   neg_r      = (const int*)d_in[4];
    const int*   neg_i      = (const int*)d_in[5];
    const int*   neg_ri     = (const int*)d_in[6];
    const int*   item_meta  = (const int*)d_in[7];
    const float* user_emb   = (const float*)d_in[8];
    const float* rel_emb    = (const float*)d_in[9];
    const float* item_emb   = (const float*)d_in[10];
    const float* item_emb_r = (const float*)d_in[11];
    const float* item_bias  = (const float*)d_in[12];
    const float* rel_bias   = (const float*)d_in[13];
    const float* meta_emb   = (const float*)d_in[14];
    const float* att_w_W    = (const float*)d_in[15];
    const float* att_v_W    = (const float*)d_in[17];

    const int B = in_sizes[0];

    precompute_w2<<<1, 64>>>(att_w_W, att_v_W);
    actr_main<<<GRID_BLOCKS, THREADS>>>(u_id, anchor_i, pos_r, pos_i, neg_r, neg_i, neg_ri,
                                        item_meta, user_emb, rel_emb, item_emb, item_emb_r,
                                        item_bias, rel_bias, meta_emb,
                                        (float*)d_out, B, 1.0f / (float)B);
}